// round 12
// baseline (speedup 1.0000x reference)
#include <cuda_runtime.h>
#include <cuda_fp16.h>
#include <cstdint>
#include <math.h>

#define VV   32000
#define EE   512
#define HH   512
#define MIDD 128
#define BB   16
#define SS   512

// scratch (device globals: no runtime allocation allowed)
__device__ float  g_Zx[BB * SS * MIDD];     // 4 MB
__device__ __half g_out16[BB * SS * EE];    // 8 MB
__device__ __half g_embed16[VV * EE];       // 32 MB
__device__ float  g_h[BB * HH];             // persisted RNN state between chunks

// ---------------------------------------------------------------- helpers
__device__ __forceinline__ void cluster_sync_all() {
    asm volatile("barrier.cluster.arrive.aligned;" ::: "memory");
    asm volatile("barrier.cluster.wait.aligned;" ::: "memory");
}
__device__ __forceinline__ uint32_t mapa_rank(uint32_t saddr, uint32_t rank) {
    uint32_t pa;
    asm volatile("mapa.shared::cluster.u32 %0, %1, %2;" : "=r"(pa) : "r"(saddr), "r"(rank));
    return pa;
}
__device__ __forceinline__ void st_async_remote(uint32_t daddr, float v, uint32_t dbar) {
    asm volatile("st.async.shared::cluster.mbarrier::complete_tx::bytes.u32 [%0], %1, [%2];"
                 :: "r"(daddr), "r"(__float_as_uint(v)), "r"(dbar) : "memory");
}
__device__ __forceinline__ void mbar_init(uint32_t a, uint32_t cnt) {
    asm volatile("mbarrier.init.shared.b64 [%0], %1;" :: "r"(a), "r"(cnt) : "memory");
}
__device__ __forceinline__ void mbar_expect_tx(uint32_t a, uint32_t bytes) {
    asm volatile("mbarrier.arrive.expect_tx.shared.b64 _, [%0], %1;"
                 :: "r"(a), "r"(bytes) : "memory");
}
__device__ __forceinline__ void mbar_wait(uint32_t a, uint32_t parity) {
    uint32_t done;
    asm volatile("{\n\t.reg .pred p;\n\t"
                 "mbarrier.try_wait.parity.acquire.cta.shared::cta.b64 p, [%1], %2;\n\t"
                 "selp.b32 %0, 1, 0, p;\n\t}"
                 : "=r"(done) : "r"(a), "r"(parity) : "memory");
    if (!done) {
        asm volatile("{\n\t.reg .pred P1;\n\t"
                     "WAIT_LOOP_%=:\n\t"
                     "mbarrier.try_wait.parity.acquire.cta.shared::cta.b64 P1, [%0], %1, 0x989680;\n\t"
                     "@P1 bra.uni WAIT_DONE_%=;\n\t"
                     "bra.uni WAIT_LOOP_%=;\n\t"
                     "WAIT_DONE_%=:\n\t}"
                     :: "r"(a), "r"(parity) : "memory");
    }
}
__device__ __forceinline__ void ldsm_x4(uint32_t& r0, uint32_t& r1, uint32_t& r2,
                                        uint32_t& r3, uint32_t a) {
    asm volatile("ldmatrix.sync.aligned.m8n8.x4.shared.b16 {%0,%1,%2,%3}, [%4];"
                 : "=r"(r0), "=r"(r1), "=r"(r2), "=r"(r3) : "r"(a));
}
__device__ __forceinline__ void mma16816(float* c, const uint32_t* a, uint32_t b0, uint32_t b1) {
    asm volatile("mma.sync.aligned.m16n8k16.row.col.f32.f16.f16.f32 "
                 "{%0,%1,%2,%3},{%4,%5,%6,%7},{%8,%9},{%0,%1,%2,%3};"
                 : "+f"(c[0]), "+f"(c[1]), "+f"(c[2]), "+f"(c[3])
                 : "r"(a[0]), "r"(a[1]), "r"(a[2]), "r"(a[3]), "r"(b0), "r"(b1));
}
__device__ __forceinline__ void cp16(uint32_t s, const void* g) {
    asm volatile("cp.async.cg.shared.global [%0], [%1], 16;" :: "r"(s), "l"(g));
}

// ---------------------------------------------------------------- K1: Zx
__global__ void __launch_bounds__(128) zx_kernel(const int* __restrict__ ids,
                                                 const float* __restrict__ embed,
                                                 const float* __restrict__ W1,
                                                 const float* __restrict__ b1) {
    __shared__ float xs[32][64];
    __shared__ float ws[64][MIDD];
    __shared__ int   sid[32];
    const int tid = threadIdx.x;
    const int t0  = blockIdx.x * 32;

    if (tid < 32) sid[tid] = ids[t0 + tid];
    __syncthreads();

    float acc[32];
#pragma unroll
    for (int m = 0; m < 32; m++) acc[m] = 0.f;

    for (int kt = 0; kt < 8; kt++) {
        const int k0 = kt * 64;
#pragma unroll
        for (int i = 0; i < 4; i++) {
            int j = tid + i * 128, m = j >> 4, q = j & 15;
            *reinterpret_cast<float4*>(&xs[m][q * 4]) =
                *reinterpret_cast<const float4*>(&embed[(size_t)sid[m] * EE + k0 + q * 4]);
        }
#pragma unroll
        for (int i = 0; i < 16; i++) {
            int j = tid + i * 128, k = j >> 5, q = j & 31;
            *reinterpret_cast<float4*>(&ws[k][q * 4]) =
                *reinterpret_cast<const float4*>(&W1[(size_t)(k0 + k) * MIDD + q * 4]);
        }
        __syncthreads();
#pragma unroll 4
        for (int kk = 0; kk < 64; kk += 4) {
            float w0 = ws[kk + 0][tid], w1 = ws[kk + 1][tid];
            float w2 = ws[kk + 2][tid], w3 = ws[kk + 3][tid];
#pragma unroll
            for (int m = 0; m < 32; m++) {
                float4 x4 = *reinterpret_cast<const float4*>(&xs[m][kk]);
                float a = acc[m];
                a = fmaf(x4.x, w0, a); a = fmaf(x4.y, w1, a);
                a = fmaf(x4.z, w2, a); a = fmaf(x4.w, w3, a);
                acc[m] = a;
            }
        }
        __syncthreads();
    }
    const float bb = b1[tid];
#pragma unroll
    for (int m = 0; m < 32; m++)
        g_Zx[(size_t)(t0 + m) * MIDD + tid] = acc[m] + bb;
}

// ---------------------------------------------------------------- rnn chunk body
// TWO batches per 4-CTA cluster (8 clusters = 32 CTAs). 256 thr/CTA.
// Weights shared across the pair; state duplicated; batch B's compute covers
// batch A's st.async/mbarrier latency.
#define NBUF   4
#define TCHUNK 128
#define ZP_P_OFF  (NBUF * 4 * 128 * 4)   // byte offset of batch-1 zparts region
#define BAR_P_OFF (NBUF * 8)             // byte offset of batch-1 mbar set

__device__ __forceinline__ void rnn_body(const float* __restrict__ hidden,
                                         const float* __restrict__ W1,
                                         const float* __restrict__ W2,
                                         int chunk) {
    __shared__ __align__(16) float h_loc[2][128];
    __shared__ __align__(16) float g_s[2][128];
    __shared__ __align__(16) float zparts[2][NBUF][4][128];
    __shared__ __align__(8)  unsigned long long mbar[2][NBUF];

    const int tid  = threadIdx.x;
    const int cl   = blockIdx.x >> 2;       // cluster id 0..7
    const int b0   = 2 * cl, b1i = 2 * cl + 1;
    const int c    = tid >> 1;
    const int half = tid & 1;
    const int t0   = chunk * TCHUNK;
    uint32_t rank;
    asm("mov.u32 %0, %%cluster_ctarank;" : "=r"(rank));

    // shared weight slices (same for both batches)
    float w1z[64], w2h[64];
#pragma unroll
    for (int i = 0; i < 64; i++)
        w1z[i] = W1[(size_t)(HH + 128 * rank + 64 * half + i) * MIDD + c];
#pragma unroll
    for (int i = 0; i < 64; i++)
        w2h[i] = W2[(size_t)(64 * half + i) * EE + 128 * rank + c];

    const uint32_t zp_loc  = (uint32_t)__cvta_generic_to_shared(&zparts[0][0][0][0]);
    const uint32_t bar_loc = (uint32_t)__cvta_generic_to_shared(&mbar[0][0]);

    if (tid == 0) {
#pragma unroll
        for (int s = 0; s < 2 * NBUF; s++) mbar_init(bar_loc + 8u * s, 1);
    }
    if (tid < 128) {
        if (chunk == 0) {
            h_loc[0][tid] = hidden[(size_t)b0  * HH + 128 * rank + tid];
            h_loc[1][tid] = hidden[(size_t)b1i * HH + 128 * rank + tid];
        } else {
            h_loc[0][tid] = g_h[(size_t)b0  * HH + 128 * rank + tid];
            h_loc[1][tid] = g_h[(size_t)b1i * HH + 128 * rank + tid];
        }
    }
    __syncthreads();
    cluster_sync_all();

    uint32_t zp_dst[4], bar_dst[4];
#pragma unroll
    for (int r = 0; r < 4; r++) {
        zp_dst[r]  = mapa_rank(zp_loc, r);
        bar_dst[r] = mapa_rank(bar_loc, r);
    }

    const float* zx0 = g_Zx + (size_t)b0  * SS * MIDD;
    const float* zx1 = g_Zx + (size_t)b1i * SS * MIDD;
    __half* out0 = g_out16 + (size_t)b0  * SS * EE + (size_t)t0 * EE + 128 * rank;
    __half* out1 = g_out16 + (size_t)b1i * SS * EE + (size_t)t0 * EE + 128 * rank;
    float zx_cur0 = (tid < 128) ? zx0[(size_t)t0 * MIDD + tid] : 0.f;
    float zx_cur1 = (tid < 128) ? zx1[(size_t)t0 * MIDD + tid] : 0.f;

    for (int t = 0; t < TCHUNK; t++) {
        const int buf = t & (NBUF - 1);
        const uint32_t ph = (uint32_t)((t >> 2) & 1);

        if (tid == 0) {
            mbar_expect_tx(bar_loc + 8u * buf,             4 * 128 * 4);
            mbar_expect_tx(bar_loc + BAR_P_OFF + 8u * buf, 4 * 128 * 4);
        }

        // ---- z partial, batch 0
        {
            float a0 = 0.f, a1 = 0.f, a2 = 0.f, a3 = 0.f;
#pragma unroll
            for (int i = 0; i < 64; i += 4) {
                float4 h4 = *reinterpret_cast<const float4*>(&h_loc[0][64 * half + i]);
                a0 = fmaf(h4.x, w1z[i + 0], a0);
                a1 = fmaf(h4.y, w1z[i + 1], a1);
                a2 = fmaf(h4.z, w1z[i + 2], a2);
                a3 = fmaf(h4.w, w1z[i + 3], a3);
            }
            float part = (a0 + a1) + (a2 + a3);
            part += __shfl_xor_sync(0xffffffffu, part, 1);
            if (half == 0) {
                const uint32_t off = (uint32_t)((buf * 4 + rank) * 128 + c) * 4u;
#pragma unroll
                for (int r = 0; r < 4; r++)
                    st_async_remote(zp_dst[r] + off, part, bar_dst[r] + 8u * buf);
            }
        }
        // ---- z partial, batch 1
        {
            float a0 = 0.f, a1 = 0.f, a2 = 0.f, a3 = 0.f;
#pragma unroll
            for (int i = 0; i < 64; i += 4) {
                float4 h4 = *reinterpret_cast<const float4*>(&h_loc[1][64 * half + i]);
                a0 = fmaf(h4.x, w1z[i + 0], a0);
                a1 = fmaf(h4.y, w1z[i + 1], a1);
                a2 = fmaf(h4.z, w1z[i + 2], a2);
                a3 = fmaf(h4.w, w1z[i + 3], a3);
            }
            float part = (a0 + a1) + (a2 + a3);
            part += __shfl_xor_sync(0xffffffffu, part, 1);
            if (half == 0) {
                const uint32_t off = (uint32_t)ZP_P_OFF + (uint32_t)((buf * 4 + rank) * 128 + c) * 4u;
#pragma unroll
                for (int r = 0; r < 4; r++)
                    st_async_remote(zp_dst[r] + off, part, bar_dst[r] + BAR_P_OFF + 8u * buf);
            }
        }

        // ---- gelu batch 0
        mbar_wait(bar_loc + 8u * buf, ph);
        if (tid < 128) {
            const float* zp = &zparts[0][buf][0][tid];
            float z = zx_cur0 + ((zp[0] + zp[128]) + (zp[256] + zp[384]));
            g_s[0][tid] = 0.5f * z * (1.0f + erff(z * 0.70710678118f));
            if (t + 1 < TCHUNK) zx_cur0 = zx0[(size_t)(t0 + t + 1) * MIDD + tid];
        }
        __syncthreads();

        // ---- h_new batch 0 (+ gelu batch 1 by lower half)
        {
            float b0a = 0.f, b1a = 0.f, b2 = 0.f, b3 = 0.f;
#pragma unroll
            for (int i = 0; i < 64; i += 4) {
                float4 g4 = *reinterpret_cast<const float4*>(&g_s[0][64 * half + i]);
                b0a = fmaf(g4.x, w2h[i + 0], b0a);
                b1a = fmaf(g4.y, w2h[i + 1], b1a);
                b2  = fmaf(g4.z, w2h[i + 2], b2);
                b3  = fmaf(g4.w, w2h[i + 3], b3);
            }
            float hp = (b0a + b1a) + (b2 + b3);
            hp += __shfl_xor_sync(0xffffffffu, hp, 1);
            if (half == 0) {
                h_loc[0][c] = hp;
                out0[(size_t)t * EE + c] = __float2half_rn(hp);
            }
        }
        mbar_wait(bar_loc + BAR_P_OFF + 8u * buf, ph);
        if (tid < 128) {
            const float* zp = &zparts[1][buf][0][tid];
            float z = zx_cur1 + ((zp[0] + zp[128]) + (zp[256] + zp[384]));
            g_s[1][tid] = 0.5f * z * (1.0f + erff(z * 0.70710678118f));
            if (t + 1 < TCHUNK) zx_cur1 = zx1[(size_t)(t0 + t + 1) * MIDD + tid];
        }
        __syncthreads();

        // ---- h_new batch 1
        {
            float b0a = 0.f, b1a = 0.f, b2 = 0.f, b3 = 0.f;
#pragma unroll
            for (int i = 0; i < 64; i += 4) {
                float4 g4 = *reinterpret_cast<const float4*>(&g_s[1][64 * half + i]);
                b0a = fmaf(g4.x, w2h[i + 0], b0a);
                b1a = fmaf(g4.y, w2h[i + 1], b1a);
                b2  = fmaf(g4.z, w2h[i + 2], b2);
                b3  = fmaf(g4.w, w2h[i + 3], b3);
            }
            float hp = (b0a + b1a) + (b2 + b3);
            hp += __shfl_xor_sync(0xffffffffu, hp, 1);
            if (half == 0) {
                h_loc[1][c] = hp;
                out1[(size_t)t * EE + c] = __float2half_rn(hp);
            }
        }
        __syncthreads();
    }

    if (tid < 128) {
        g_h[(size_t)b0  * HH + 128 * rank + tid] = h_loc[0][tid];
        g_h[(size_t)b1i * HH + 128 * rank + tid] = h_loc[1][tid];
    }
    cluster_sync_all();
}

// ---------------------------------------------------------------- gemm chunk body (exact R8 engine)
// BM=128, BN=256, BK=64, 3 stages, 256 thr (8 warps, 64x64), frag db, fp32 accum.
#define ASTRIDE 72                       // halves per smem row (144B)
#define A_ST    (128 * ASTRIDE)
#define B_ST    (256 * ASTRIDE)
#define GSMEM   ((3 * (A_ST + B_ST)) * 2)   // 165888 B

__device__ __forceinline__ void gemm_body(const float* __restrict__ cls_b,
                                          float* __restrict__ C,
                                          int gb, int chunk) {
    extern __shared__ __align__(16) __half sm[];
    __half* As = sm;
    __half* Bs = sm + 3 * A_ST;

    const int tid = threadIdx.x;
    const int wid = tid >> 5, lane = tid & 31;
    const int bidx = gb / 125, nb = gb % 125;
    const int R0 = bidx * SS + chunk * 128;
    const int N0 = nb * 256;

    const __half* Ag = g_out16   + (size_t)R0 * EE;
    const __half* Bg = g_embed16 + (size_t)N0 * EE;

    const int warp_m = (wid >> 2) * 64;
    const int warp_n = (wid & 3) * 64;

    float c[4][8][4];
#pragma unroll
    for (int i = 0; i < 4; i++)
#pragma unroll
        for (int j = 0; j < 8; j++)
#pragma unroll
            for (int q = 0; q < 4; q++) c[i][j][q] = 0.f;

    const uint32_t asb = (uint32_t)__cvta_generic_to_shared(As);
    const uint32_t bsb = (uint32_t)__cvta_generic_to_shared(Bs);

    auto load_tile = [&](int kt, int st) {
        const uint32_t ab = asb + (uint32_t)(st * A_ST) * 2;
        const uint32_t bb = bsb + (uint32_t)(st * B_ST) * 2;
#pragma unroll
        for (int i = 0; i < 4; i++) {           // A: 1024 chunks of 16B
            int cc = tid + i * 256;
            int r = cc >> 3, sg = cc & 7;
            cp16(ab + (uint32_t)(r * ASTRIDE + sg * 8) * 2,
                 Ag + (size_t)r * EE + kt * 64 + sg * 8);
        }
#pragma unroll
        for (int i = 0; i < 8; i++) {           // B: 2048 chunks of 16B
            int cc = tid + i * 256;
            int r = cc >> 3, sg = cc & 7;
            cp16(bb + (uint32_t)(r * ASTRIDE + sg * 8) * 2,
                 Bg + (size_t)r * EE + kt * 64 + sg * 8);
        }
        asm volatile("cp.async.commit_group;");
    };

    uint32_t afr[2][4][4], bfr[2][8][2];

    auto ldsm_batch = [&](int kk, uint32_t ab, uint32_t bb, int pb) {
        const uint32_t koff = (uint32_t)(kk * 16 + ((lane >> 4) << 3));
#pragma unroll
        for (int i = 0; i < 4; i++) {
            uint32_t addr = ab + (uint32_t)((warp_m + i * 16 + (lane & 15)) * ASTRIDE + koff) * 2;
            ldsm_x4(afr[pb][i][0], afr[pb][i][1], afr[pb][i][2], afr[pb][i][3], addr);
        }
#pragma unroll
        for (int j2 = 0; j2 < 4; j2++) {
            uint32_t r0, r1, r2, r3;
            uint32_t addr = bb + (uint32_t)((warp_n + j2 * 16 + (lane & 15)) * ASTRIDE + koff) * 2;
            ldsm_x4(r0, r1, r2, r3, addr);
            bfr[pb][2 * j2 + 0][0] = r0; bfr[pb][2 * j2 + 0][1] = r2;
            bfr[pb][2 * j2 + 1][0] = r1; bfr[pb][2 * j2 + 1][1] = r3;
        }
    };

    load_tile(0, 0);
    load_tile(1, 1);

    for (int kt = 0; kt < 8; kt++) {
        const int st = kt % 3;
        if (kt < 7) asm volatile("cp.async.wait_group 1;");
        else        asm volatile("cp.async.wait_group 0;");
        __syncthreads();

        if (kt + 2 < 8) load_tile(kt + 2, (kt + 2) % 3);

        const uint32_t ab = asb + (uint32_t)(st * A_ST) * 2;
        const uint32_t bb = bsb + (uint32_t)(st * B_ST) * 2;

        ldsm_batch(0, ab, bb, 0);
#pragma unroll
        for (int kk = 0; kk < 4; kk++) {
            const int cur = kk & 1;
            if (kk < 3) ldsm_batch(kk + 1, ab, bb, cur ^ 1);
#pragma unroll
            for (int i = 0; i < 4; i++)
#pragma unroll
                for (int j = 0; j < 8; j++)
                    mma16816(c[i][j], afr[cur][i], bfr[cur][j][0], bfr[cur][j][1]);
        }
        __syncthreads();
    }

#pragma unroll
    for (int i = 0; i < 4; i++) {
        int rm0 = R0 + warp_m + i * 16 + (lane >> 2);
#pragma unroll
        for (int j = 0; j < 8; j++) {
            int gn = N0 + warp_n + j * 8 + (lane & 3) * 2;
            float2 bv = *reinterpret_cast<const float2*>(&cls_b[gn]);
            float2 v0 = make_float2(c[i][j][0] + bv.x, c[i][j][1] + bv.y);
            float2 v1 = make_float2(c[i][j][2] + bv.x, c[i][j][3] + bv.y);
            *reinterpret_cast<float2*>(&C[(size_t)rm0 * VV + gn])       = v0;
            *reinterpret_cast<float2*>(&C[(size_t)(rm0 + 8) * VV + gn]) = v1;
        }
    }
}

// ---------------------------------------------------------------- fused phase kernel
// blockIdx < n_rnn             : rnn chunk rnn_chunk (2 batches per cluster)
// blockIdx >= n_rnn, chunk>=0  : gemm chunk gemm_chunk
// blockIdx >= n_rnn, chunk==-2 : embed fp32->fp16 conversion (P0 only)
__global__ void __cluster_dims__(4, 1, 1) __launch_bounds__(256, 1)
phase_kernel(const float* __restrict__ hidden,
             const float* __restrict__ W1,
             const float* __restrict__ W2,
             const float* __restrict__ cls_b,
             const float* __restrict__ embed,
             float* __restrict__ C,
             int n_rnn, int rnn_chunk, int gemm_chunk) {
    if ((int)blockIdx.x < n_rnn) {
        rnn_body(hidden, W1, W2, rnn_chunk);
    } else if (gemm_chunk >= 0) {
        gemm_body(cls_b, C, (int)blockIdx.x - n_rnn, gemm_chunk);
    } else if (gemm_chunk == -2) {
        int i = ((int)blockIdx.x - n_rnn) * (int)blockDim.x + (int)threadIdx.x;
        int stride = ((int)gridDim.x - n_rnn) * (int)blockDim.x;
        const int n4 = (VV * EE) / 4;
        __half2* dst = reinterpret_cast<__half2*>(g_embed16);
        const float4* s4 = reinterpret_cast<const float4*>(embed);
        for (; i < n4; i += stride) {
            float4 v = s4[i];
            dst[2 * i + 0] = __floats2half2_rn(v.x, v.y);
            dst[2 * i + 1] = __floats2half2_rn(v.z, v.w);
        }
    }
}

// ---------------------------------------------------------------- launch
extern "C" void kernel_launch(void* const* d_in, const int* in_sizes, int n_in,
                              void* d_out, int out_size) {
    const int*   ids    = (const int*)d_in[0];
    const float* hidden = (const float*)d_in[1];
    const float* embed  = (const float*)d_in[2];
    const float* W1     = (const float*)d_in[3];
    const float* b1     = (const float*)d_in[4];
    const float* W2     = (const float*)d_in[5];
    const float* cls_b  = (const float*)d_in[6];
    float* out = (float*)d_out;

    cudaFuncSetAttribute(phase_kernel, cudaFuncAttributeMaxDynamicSharedMemorySize, GSMEM);

    zx_kernel<<<(BB * SS) / 32, 128>>>(ids, embed, W1, b1);

    // P0: rnn chunk 0 (32 CTAs) + embed conversion on the spare SMs
    phase_kernel<<<148, 256, GSMEM>>>(hidden, W1, W2, cls_b, embed, out, 32, 0, -2);
    // P1..P3: rnn chunk c overlapped with gemm chunk c-1
    phase_kernel<<<2032, 256, GSMEM>>>(hidden, W1, W2, cls_b, embed, out, 32, 1, 0);
    phase_kernel<<<2032, 256, GSMEM>>>(hidden, W1, W2, cls_b, embed, out, 32, 2, 1);
    phase_kernel<<<2032, 256, GSMEM>>>(hidden, W1, W2, cls_b, embed, out, 32, 3, 2);
    // P4: last gemm chunk
    phase_kernel<<<2000, 256, GSMEM>>>(hidden, W1, W2, cls_b, embed, out, 0, -1, 3);
}

// round 13
// speedup vs baseline: 1.0646x; 1.0646x over previous
#include <cuda_runtime.h>
#include <cuda_fp16.h>
#include <cstdint>
#include <math.h>

#define VV   32000
#define EE   512
#define HH   512
#define MIDD 128
#define BB   16
#define SS   512

// scratch (device globals: no runtime allocation allowed)
__device__ float  g_Zx[BB * SS * MIDD];     // 4 MB
__device__ __half g_out16[BB * SS * EE];    // 8 MB
__device__ __half g_embed16[VV * EE];       // 32 MB
__device__ float  g_h[BB * HH];             // persisted RNN state between chunks

// ---------------------------------------------------------------- helpers
__device__ __forceinline__ void cluster_sync_all() {
    asm volatile("barrier.cluster.arrive.aligned;" ::: "memory");
    asm volatile("barrier.cluster.wait.aligned;" ::: "memory");
}
__device__ __forceinline__ uint32_t mapa_rank(uint32_t saddr, uint32_t rank) {
    uint32_t pa;
    asm volatile("mapa.shared::cluster.u32 %0, %1, %2;" : "=r"(pa) : "r"(saddr), "r"(rank));
    return pa;
}
__device__ __forceinline__ void st_async_remote(uint32_t daddr, float v, uint32_t dbar) {
    asm volatile("st.async.shared::cluster.mbarrier::complete_tx::bytes.u32 [%0], %1, [%2];"
                 :: "r"(daddr), "r"(__float_as_uint(v)), "r"(dbar) : "memory");
}
__device__ __forceinline__ void mbar_init(uint32_t a, uint32_t cnt) {
    asm volatile("mbarrier.init.shared.b64 [%0], %1;" :: "r"(a), "r"(cnt) : "memory");
}
__device__ __forceinline__ void mbar_expect_tx(uint32_t a, uint32_t bytes) {
    asm volatile("mbarrier.arrive.expect_tx.shared.b64 _, [%0], %1;"
                 :: "r"(a), "r"(bytes) : "memory");
}
__device__ __forceinline__ void mbar_wait(uint32_t a, uint32_t parity) {
    uint32_t done;
    asm volatile("{\n\t.reg .pred p;\n\t"
                 "mbarrier.try_wait.parity.acquire.cta.shared::cta.b64 p, [%1], %2;\n\t"
                 "selp.b32 %0, 1, 0, p;\n\t}"
                 : "=r"(done) : "r"(a), "r"(parity) : "memory");
    if (!done) {
        asm volatile("{\n\t.reg .pred P1;\n\t"
                     "WAIT_LOOP_%=:\n\t"
                     "mbarrier.try_wait.parity.acquire.cta.shared::cta.b64 P1, [%0], %1, 0x989680;\n\t"
                     "@P1 bra.uni WAIT_DONE_%=;\n\t"
                     "bra.uni WAIT_LOOP_%=;\n\t"
                     "WAIT_DONE_%=:\n\t}"
                     :: "r"(a), "r"(parity) : "memory");
    }
}
__device__ __forceinline__ void ldsm_x4(uint32_t& r0, uint32_t& r1, uint32_t& r2,
                                        uint32_t& r3, uint32_t a) {
    asm volatile("ldmatrix.sync.aligned.m8n8.x4.shared.b16 {%0,%1,%2,%3}, [%4];"
                 : "=r"(r0), "=r"(r1), "=r"(r2), "=r"(r3) : "r"(a));
}
__device__ __forceinline__ void mma16816(float* c, const uint32_t* a, uint32_t b0, uint32_t b1) {
    asm volatile("mma.sync.aligned.m16n8k16.row.col.f32.f16.f16.f32 "
                 "{%0,%1,%2,%3},{%4,%5,%6,%7},{%8,%9},{%0,%1,%2,%3};"
                 : "+f"(c[0]), "+f"(c[1]), "+f"(c[2]), "+f"(c[3])
                 : "r"(a[0]), "r"(a[1]), "r"(a[2]), "r"(a[3]), "r"(b0), "r"(b1));
}
__device__ __forceinline__ void cp16(uint32_t s, const void* g) {
    asm volatile("cp.async.cg.shared.global [%0], [%1], 16;" :: "r"(s), "l"(g));
}

// ---------------------------------------------------------------- zx body (256-thread fused version)
// Computes Zx[token0 .. token0+32) [tokens are (b*512 + t) indices].
// Threads >=128 idle through the barriers (all threads hit __syncthreads).
__device__ __forceinline__ void zx_body(const int* __restrict__ ids,
                                        const float* __restrict__ embed,
                                        const float* __restrict__ W1,
                                        const float* __restrict__ b1,
                                        int token0) {
    __shared__ float xs[32][64];
    __shared__ float ws[64][MIDD];
    __shared__ int   sid[32];
    const int tid = threadIdx.x;

    if (tid < 32) sid[tid] = ids[token0 + tid];
    __syncthreads();

    float acc[32];
#pragma unroll
    for (int m = 0; m < 32; m++) acc[m] = 0.f;

    for (int kt = 0; kt < 8; kt++) {
        const int k0 = kt * 64;
        if (tid < 128) {
#pragma unroll
            for (int i = 0; i < 4; i++) {
                int j = tid + i * 128, m = j >> 4, q = j & 15;
                *reinterpret_cast<float4*>(&xs[m][q * 4]) =
                    *reinterpret_cast<const float4*>(&embed[(size_t)sid[m] * EE + k0 + q * 4]);
            }
#pragma unroll
            for (int i = 0; i < 16; i++) {
                int j = tid + i * 128, k = j >> 5, q = j & 31;
                *reinterpret_cast<float4*>(&ws[k][q * 4]) =
                    *reinterpret_cast<const float4*>(&W1[(size_t)(k0 + k) * MIDD + q * 4]);
            }
        }
        __syncthreads();
        if (tid < 128) {
#pragma unroll 4
            for (int kk = 0; kk < 64; kk += 4) {
                float w0 = ws[kk + 0][tid], w1 = ws[kk + 1][tid];
                float w2 = ws[kk + 2][tid], w3 = ws[kk + 3][tid];
#pragma unroll
                for (int m = 0; m < 32; m++) {
                    float4 x4 = *reinterpret_cast<const float4*>(&xs[m][kk]);
                    float a = acc[m];
                    a = fmaf(x4.x, w0, a); a = fmaf(x4.y, w1, a);
                    a = fmaf(x4.z, w2, a); a = fmaf(x4.w, w3, a);
                    acc[m] = a;
                }
            }
        }
        __syncthreads();
    }
    if (tid < 128) {
        const float bb = b1[tid];
#pragma unroll
        for (int m = 0; m < 32; m++)
            g_Zx[(size_t)(token0 + m) * MIDD + tid] = acc[m] + bb;
    }
}

// zx chunk -> token0 map: chunk c covers t in [128c, 128c+128) for all 16 batches.
// Block i in [0,64): batch = i>>2, t = 128c + (i&3)*32.
__device__ __forceinline__ int zx_token0(int chunk, int i) {
    return (i >> 2) * SS + chunk * 128 + (i & 3) * 32;
}

// ---------------------------------------------------------------- cvt body (grid-stride over spare blocks)
__device__ __forceinline__ void cvt_body(const float* __restrict__ src, int bid, int nblocks) {
    int i = bid * (int)blockDim.x + (int)threadIdx.x;
    int stride = nblocks * (int)blockDim.x;
    const int n4 = (VV * EE) / 4;
    __half2* dst = reinterpret_cast<__half2*>(g_embed16);
    const float4* s4 = reinterpret_cast<const float4*>(src);
    for (; i < n4; i += stride) {
        float4 v = s4[i];
        dst[2 * i + 0] = __floats2half2_rn(v.x, v.y);
        dst[2 * i + 1] = __floats2half2_rn(v.z, v.w);
    }
}

// ---------------------------------------------------------------- rnn chunk body (128 steps, 256 thr) — R8 exact
#define NBUF   4
#define TCHUNK 128
__device__ __forceinline__ void rnn_body(const float* __restrict__ hidden,
                                         const float* __restrict__ W1,
                                         const float* __restrict__ W2,
                                         int chunk) {
    __shared__ __align__(16) float h_loc[128];
    __shared__ __align__(16) float g_s[128];
    __shared__ __align__(16) float zparts[NBUF][4][128];
    __shared__ __align__(8)  unsigned long long mbar[NBUF];

    const int tid  = threadIdx.x;
    const int b    = blockIdx.x >> 2;
    const int c    = tid >> 1;
    const int half = tid & 1;
    const int t0   = chunk * TCHUNK;
    uint32_t rank;
    asm("mov.u32 %0, %%cluster_ctarank;" : "=r"(rank));

    float w1z[64], w2h[64];
#pragma unroll
    for (int i = 0; i < 64; i++)
        w1z[i] = W1[(size_t)(HH + 128 * rank + 64 * half + i) * MIDD + c];
#pragma unroll
    for (int i = 0; i < 64; i++)
        w2h[i] = W2[(size_t)(64 * half + i) * EE + 128 * rank + c];

    const uint32_t zp_loc  = (uint32_t)__cvta_generic_to_shared(&zparts[0][0][0]);
    const uint32_t bar_loc = (uint32_t)__cvta_generic_to_shared(&mbar[0]);

    if (tid == 0) {
#pragma unroll
        for (int s = 0; s < NBUF; s++) mbar_init(bar_loc + 8u * s, 1);
    }
    if (tid < 128) {
        h_loc[tid] = (chunk == 0) ? hidden[(size_t)b * HH + 128 * rank + tid]
                                  : g_h[(size_t)b * HH + 128 * rank + tid];
    }
    __syncthreads();
    cluster_sync_all();

    uint32_t zp_dst[4], bar_dst[4];
#pragma unroll
    for (int r = 0; r < 4; r++) {
        zp_dst[r]  = mapa_rank(zp_loc, r);
        bar_dst[r] = mapa_rank(bar_loc, r);
    }

    const float* zx_row  = g_Zx    + (size_t)b * SS * MIDD;
    __half*      out_row = g_out16 + (size_t)b * SS * EE + (size_t)t0 * EE + 128 * rank;
    float zx_cur = (tid < 128) ? zx_row[(size_t)t0 * MIDD + tid] : 0.f;

    for (int t = 0; t < TCHUNK; t++) {
        const int buf = t & (NBUF - 1);
        const uint32_t ph = (uint32_t)((t >> 2) & 1);

        if (tid == 0) mbar_expect_tx(bar_loc + 8u * buf, 4 * 128 * 4);

        float a0 = 0.f, a1 = 0.f, a2 = 0.f, a3 = 0.f;
#pragma unroll
        for (int i = 0; i < 64; i += 4) {
            float4 h4 = *reinterpret_cast<const float4*>(&h_loc[64 * half + i]);
            a0 = fmaf(h4.x, w1z[i + 0], a0);
            a1 = fmaf(h4.y, w1z[i + 1], a1);
            a2 = fmaf(h4.z, w1z[i + 2], a2);
            a3 = fmaf(h4.w, w1z[i + 3], a3);
        }
        float part = (a0 + a1) + (a2 + a3);
        part += __shfl_xor_sync(0xffffffffu, part, 1);

        if (half == 0) {
            const uint32_t off = (uint32_t)((buf * 4 + rank) * 128 + c) * 4u;
#pragma unroll
            for (int r = 0; r < 4; r++)
                st_async_remote(zp_dst[r] + off, part, bar_dst[r] + 8u * buf);
        }

        mbar_wait(bar_loc + 8u * buf, ph);

        if (tid < 128) {
            const float* zp = &zparts[buf][0][tid];
            float z = zx_cur + ((zp[0] + zp[128]) + (zp[256] + zp[384]));
            g_s[tid] = 0.5f * z * (1.0f + erff(z * 0.70710678118f));
            if (t + 1 < TCHUNK) zx_cur = zx_row[(size_t)(t0 + t + 1) * MIDD + tid];
        }
        __syncthreads();

        float b0 = 0.f, b1a = 0.f, b2 = 0.f, b3 = 0.f;
#pragma unroll
        for (int i = 0; i < 64; i += 4) {
            float4 g4 = *reinterpret_cast<const float4*>(&g_s[64 * half + i]);
            b0  = fmaf(g4.x, w2h[i + 0], b0);
            b1a = fmaf(g4.y, w2h[i + 1], b1a);
            b2  = fmaf(g4.z, w2h[i + 2], b2);
            b3  = fmaf(g4.w, w2h[i + 3], b3);
        }
        float hp = (b0 + b1a) + (b2 + b3);
        hp += __shfl_xor_sync(0xffffffffu, hp, 1);
        if (half == 0) {
            h_loc[c] = hp;
            out_row[(size_t)t * EE + c] = __float2half_rn(hp);
        }
        __syncthreads();
    }

    if (tid < 128) g_h[(size_t)b * HH + 128 * rank + tid] = h_loc[tid];
    cluster_sync_all();
}

// ---------------------------------------------------------------- gemm chunk body — R8 exact
// BM=128, BN=256, BK=64, 3 stages, 256 thr (8 warps, 64x64), frag db, fp32 accum.
#define ASTRIDE 72                       // halves per smem row (144B)
#define A_ST    (128 * ASTRIDE)
#define B_ST    (256 * ASTRIDE)
#define GSMEM   ((3 * (A_ST + B_ST)) * 2)   // 165888 B

__device__ __forceinline__ void gemm_body(const float* __restrict__ cls_b,
                                          float* __restrict__ C,
                                          int gb, int chunk) {
    extern __shared__ __align__(16) __half sm[];
    __half* As = sm;
    __half* Bs = sm + 3 * A_ST;

    const int tid = threadIdx.x;
    const int wid = tid >> 5, lane = tid & 31;
    const int bidx = gb / 125, nb = gb % 125;
    const int R0 = bidx * SS + chunk * 128;
    const int N0 = nb * 256;

    const __half* Ag = g_out16   + (size_t)R0 * EE;
    const __half* Bg = g_embed16 + (size_t)N0 * EE;

    const int warp_m = (wid >> 2) * 64;
    const int warp_n = (wid & 3) * 64;

    float c[4][8][4];
#pragma unroll
    for (int i = 0; i < 4; i++)
#pragma unroll
        for (int j = 0; j < 8; j++)
#pragma unroll
            for (int q = 0; q < 4; q++) c[i][j][q] = 0.f;

    const uint32_t asb = (uint32_t)__cvta_generic_to_shared(As);
    const uint32_t bsb = (uint32_t)__cvta_generic_to_shared(Bs);

    auto load_tile = [&](int kt, int st) {
        const uint32_t ab = asb + (uint32_t)(st * A_ST) * 2;
        const uint32_t bb = bsb + (uint32_t)(st * B_ST) * 2;
#pragma unroll
        for (int i = 0; i < 4; i++) {           // A: 1024 chunks of 16B
            int cc = tid + i * 256;
            int r = cc >> 3, sg = cc & 7;
            cp16(ab + (uint32_t)(r * ASTRIDE + sg * 8) * 2,
                 Ag + (size_t)r * EE + kt * 64 + sg * 8);
        }
#pragma unroll
        for (int i = 0; i < 8; i++) {           // B: 2048 chunks of 16B
            int cc = tid + i * 256;
            int r = cc >> 3, sg = cc & 7;
            cp16(bb + (uint32_t)(r * ASTRIDE + sg * 8) * 2,
                 Bg + (size_t)r * EE + kt * 64 + sg * 8);
        }
        asm volatile("cp.async.commit_group;");
    };

    uint32_t afr[2][4][4], bfr[2][8][2];

    auto ldsm_batch = [&](int kk, uint32_t ab, uint32_t bb, int pb) {
        const uint32_t koff = (uint32_t)(kk * 16 + ((lane >> 4) << 3));
#pragma unroll
        for (int i = 0; i < 4; i++) {
            uint32_t addr = ab + (uint32_t)((warp_m + i * 16 + (lane & 15)) * ASTRIDE + koff) * 2;
            ldsm_x4(afr[pb][i][0], afr[pb][i][1], afr[pb][i][2], afr[pb][i][3], addr);
        }
#pragma unroll
        for (int j2 = 0; j2 < 4; j2++) {
            uint32_t r0, r1, r2, r3;
            uint32_t addr = bb + (uint32_t)((warp_n + j2 * 16 + (lane & 15)) * ASTRIDE + koff) * 2;
            ldsm_x4(r0, r1, r2, r3, addr);
            bfr[pb][2 * j2 + 0][0] = r0; bfr[pb][2 * j2 + 0][1] = r2;
            bfr[pb][2 * j2 + 1][0] = r1; bfr[pb][2 * j2 + 1][1] = r3;
        }
    };

    load_tile(0, 0);
    load_tile(1, 1);

    for (int kt = 0; kt < 8; kt++) {
        const int st = kt % 3;
        if (kt < 7) asm volatile("cp.async.wait_group 1;");
        else        asm volatile("cp.async.wait_group 0;");
        __syncthreads();

        if (kt + 2 < 8) load_tile(kt + 2, (kt + 2) % 3);

        const uint32_t ab = asb + (uint32_t)(st * A_ST) * 2;
        const uint32_t bb = bsb + (uint32_t)(st * B_ST) * 2;

        ldsm_batch(0, ab, bb, 0);
#pragma unroll
        for (int kk = 0; kk < 4; kk++) {
            const int cur = kk & 1;
            if (kk < 3) ldsm_batch(kk + 1, ab, bb, cur ^ 1);
#pragma unroll
            for (int i = 0; i < 4; i++)
#pragma unroll
                for (int j = 0; j < 8; j++)
                    mma16816(c[i][j], afr[cur][i], bfr[cur][j][0], bfr[cur][j][1]);
        }
        __syncthreads();
    }

#pragma unroll
    for (int i = 0; i < 4; i++) {
        int rm0 = R0 + warp_m + i * 16 + (lane >> 2);
#pragma unroll
        for (int j = 0; j < 8; j++) {
            int gn = N0 + warp_n + j * 8 + (lane & 3) * 2;
            float2 bv = *reinterpret_cast<const float2*>(&cls_b[gn]);
            float2 v0 = make_float2(c[i][j][0] + bv.x, c[i][j][1] + bv.y);
            float2 v1 = make_float2(c[i][j][2] + bv.x, c[i][j][3] + bv.y);
            *reinterpret_cast<float2*>(&C[(size_t)rm0 * VV + gn])       = v0;
            *reinterpret_cast<float2*>(&C[(size_t)(rm0 + 8) * VV + gn]) = v1;
        }
    }
}

// ---------------------------------------------------------------- fused phase kernel
// bid <  n_rnn : rnn chunk rnn_chunk
// bid >= n_rnn : mode = gemm_chunk
//    >= 0 : gemm chunk
//    -3   : zx chunk 0 (64 blocks)
//    -4   : P0 combo — first 192 spare blocks: zx chunks 1..3; rest: cvt
__global__ void __cluster_dims__(4, 1, 1) __launch_bounds__(256, 1)
phase_kernel(const float* __restrict__ hidden,
             const float* __restrict__ W1,
             const float* __restrict__ W2,
             const float* __restrict__ cls_b,
             const float* __restrict__ embed,
             const int*   __restrict__ ids,
             const float* __restrict__ b1,
             float* __restrict__ C,
             int n_rnn, int rnn_chunk, int gemm_chunk) {
    if ((int)blockIdx.x < n_rnn) {
        rnn_body(hidden, W1, W2, rnn_chunk);
    } else if (gemm_chunk >= 0) {
        gemm_body(cls_b, C, (int)blockIdx.x - n_rnn, gemm_chunk);
    } else if (gemm_chunk == -3) {
        int i = (int)blockIdx.x - n_rnn;            // [0,64)
        zx_body(ids, embed, W1, b1, zx_token0(0, i));
    } else if (gemm_chunk == -4) {
        int j = (int)blockIdx.x - n_rnn;
        if (j < 192) {
            zx_body(ids, embed, W1, b1, zx_token0(1 + j / 64, j % 64));
        } else {
            cvt_body(embed, j - 192, (int)gridDim.x - n_rnn - 192);
        }
    }
}

// ---------------------------------------------------------------- launch
extern "C" void kernel_launch(void* const* d_in, const int* in_sizes, int n_in,
                              void* d_out, int out_size) {
    const int*   ids    = (const int*)d_in[0];
    const float* hidden = (const float*)d_in[1];
    const float* embed  = (const float*)d_in[2];
    const float* W1     = (const float*)d_in[3];
    const float* b1     = (const float*)d_in[4];
    const float* W2     = (const float*)d_in[5];
    const float* cls_b  = (const float*)d_in[6];
    float* out = (float*)d_out;

    cudaFuncSetAttribute(phase_kernel, cudaFuncAttributeMaxDynamicSharedMemorySize, GSMEM);

    // zx chunk 0 only (t in [0,128)) — fast serial prologue
    phase_kernel<<<64, 256, GSMEM>>>(hidden, W1, W2, cls_b, embed, ids, b1, out, 0, -1, -3);
    // P0: rnn chunk 0 + zx chunks 1..3 + embed conversion on spare SMs
    phase_kernel<<<2048, 256, GSMEM>>>(hidden, W1, W2, cls_b, embed, ids, b1, out, 64, 0, -4);
    // P1..P3: rnn chunk c overlapped with gemm chunk c-1
    phase_kernel<<<2064, 256, GSMEM>>>(hidden, W1, W2, cls_b, embed, ids, b1, out, 64, 1, 0);
    phase_kernel<<<2064, 256, GSMEM>>>(hidden, W1, W2, cls_b, embed, ids, b1, out, 64, 2, 1);
    phase_kernel<<<2064, 256, GSMEM>>>(hidden, W1, W2, cls_b, embed, ids, b1, out, 64, 3, 2);
    // P4: last gemm chunk
    phase_kernel<<<2000, 256, GSMEM>>>(hidden, W1, W2, cls_b, embed, ids, b1, out, 0, -1, 3);
}